// round 8
// baseline (speedup 1.0000x reference)
#include <cuda_runtime.h>
#include <cstdint>
#include <cstddef>

// BioConvolution: 256 independent GEMMs  C_l[64,128] = A_l[64,1024] * B_l[1024,128]
//   A_l[m][k] = X[m, r*4+i, c*4+j, ch]  (k = i*256+j*64+ch, l = r*16+c)
//   B_l[k][f] = filters[l*131072 + k*128 + f]
//   out[(m*256+l)*128+f] = relu(C + bias[f])
//
// Round 8: the fb-register pipeline capped per-SM BW at ~42GB/s (12 LDG.128
// in flight per warp per iteration, latency-bound). Replace LDG+regs with
// cp.async f32 -> 3-stage staging ring (depth-2 in flight, zero registers),
// plus an in-smem repack pass (LDS f32 -> cvt -> STS f16) feeding the
// verified ldmatrix + mma.m16n8k16 fp16 compute (K=32 chunks).

namespace {

constexpr int NST = 32;              // K chunks of 32 floats
// f32 staging: 3 stages x (A 64x32 f32 = 8192B, B 32x128 f32 = 16384B)
constexpr int STG_CH   = 24576;
constexpr int F16_BASE = 3 * STG_CH;          // 73728
// f16 ring: 2 stages x (A 64x40 halves = 5120B, B 32x136 halves = 8704B)
constexpr int F16_STG  = 13824;
constexpr int SMEM_BYTES = F16_BASE + 2 * F16_STG;  // 101376

__device__ __forceinline__ uint32_t smem_u32(const void* p) {
    return static_cast<uint32_t>(__cvta_generic_to_shared(p));
}
__device__ __forceinline__ void cp16(uint32_t s, const float* g) {
    asm volatile("cp.async.cg.shared.global [%0], [%1], 16;" :: "r"(s), "l"(g));
}
__device__ __forceinline__ void cp_commit() {
    asm volatile("cp.async.commit_group;");
}
template <int N>
__device__ __forceinline__ void cp_wait() {
    asm volatile("cp.async.wait_group %0;" :: "n"(N));
}
__device__ __forceinline__ float4 lds128f(uint32_t a) {
    float4 v;
    asm volatile("ld.shared.v4.f32 {%0,%1,%2,%3}, [%4];"
                 : "=f"(v.x), "=f"(v.y), "=f"(v.z), "=f"(v.w) : "r"(a));
    return v;
}
__device__ __forceinline__ uint32_t pack_h2(float lo, float hi) {
    uint32_t d;
    asm("cvt.rn.f16x2.f32 %0, %1, %2;" : "=r"(d) : "f"(hi), "f"(lo));
    return d;
}
__device__ __forceinline__ void sts64(uint32_t a, uint32_t x, uint32_t y) {
    asm volatile("st.shared.v2.b32 [%0], {%1,%2};" :: "r"(a), "r"(x), "r"(y));
}
__device__ __forceinline__ void ldmx4(uint32_t* r, uint32_t a) {
    asm volatile("ldmatrix.sync.aligned.m8n8.x4.shared.b16 {%0,%1,%2,%3}, [%4];"
                 : "=r"(r[0]), "=r"(r[1]), "=r"(r[2]), "=r"(r[3]) : "r"(a));
}
__device__ __forceinline__ void ldmx4t(uint32_t* r, uint32_t a) {
    asm volatile("ldmatrix.sync.aligned.m8n8.x4.trans.shared.b16 {%0,%1,%2,%3}, [%4];"
                 : "=r"(r[0]), "=r"(r[1]), "=r"(r[2]), "=r"(r[3]) : "r"(a));
}
__device__ __forceinline__ void mma_f16(float* c, const uint32_t* a, const uint32_t* b) {
    asm volatile(
        "mma.sync.aligned.m16n8k16.row.col.f32.f16.f16.f32 "
        "{%0,%1,%2,%3}, {%4,%5,%6,%7}, {%8,%9}, {%0,%1,%2,%3};"
        : "+f"(c[0]), "+f"(c[1]), "+f"(c[2]), "+f"(c[3])
        : "r"(a[0]), "r"(a[1]), "r"(a[2]), "r"(a[3]), "r"(b[0]), "r"(b[1]));
}

__global__ __launch_bounds__(256, 2)
void bioconv_cpa_kernel(const float* __restrict__ X,
                        const float* __restrict__ filt,
                        const float* __restrict__ bias,
                        float* __restrict__ out) {
    extern __shared__ __align__(16) char smem[];
    const uint32_t sb = smem_u32(smem);

    const int tid = threadIdx.x;
    const int l   = blockIdx.x;
    const int r   = l >> 4;
    const int cc  = l & 15;

    const float* gA0 = X + (size_t)r * 16384 + (size_t)cc * 256;
    const float* gB0 = filt + (size_t)l * 131072;

    // ---- compute mapping: 8 warps, 2(M) x 4(N), warp tile 32x32 ----
    const int lane = tid & 31;
    const int wid  = tid >> 5;
    const int wm   = wid >> 2;
    const int wn   = wid & 3;
    const int g    = lane >> 2;
    const int t4   = lane & 3;

    // byte offsets within an f16 stage (A stride 80B, B stride 272B)
    const uint32_t a_off = (uint32_t)((wm * 32 + (lane & 15)) * 80 + (lane >> 4) * 16);
    const uint32_t b_off = 5120u +
        (uint32_t)((lane & 15) * 272 + (wn * 32 + ((lane >> 4) & 1) * 8) * 2);

    float acc[2][4][4];
#pragma unroll
    for (int i = 0; i < 2; ++i)
#pragma unroll
        for (int j = 0; j < 4; ++j)
#pragma unroll
            for (int k = 0; k < 4; ++k) acc[i][j][k] = 0.f;

    // ---- cp.async issue of chunk t into staging[(t)%3] ----
    auto issue_chunk = [&](int t) {
        const uint32_t sA = sb + (t % 3) * STG_CH;
        const float* ga = gA0 + (t >> 3) * 4096 + ((t >> 1) & 3) * 64 + (t & 1) * 32;
#pragma unroll
        for (int v = 0; v < 2; ++v) {
            const int id = v * 256 + tid;
            const int row = id >> 3, c4 = id & 7;
            cp16(sA + row * 128 + c4 * 16,
                 ga + (size_t)row * 262144 + c4 * 4);
        }
        const float* gb = gB0 + (size_t)t * 4096;
#pragma unroll
        for (int v = 0; v < 4; ++v) {
            const int id = v * 256 + tid;
            const int row = id >> 5, c4 = id & 31;
            cp16(sA + 8192 + row * 512 + c4 * 16, gb + row * 128 + c4 * 4);
        }
    };

    // ---- repack chunk t: staging f32 -> f16 ring[(t)&1] ----
    auto repack = [&](int t) {
        const uint32_t src = sb + (t % 3) * STG_CH;
        const uint32_t dst = sb + F16_BASE + (t & 1) * F16_STG;
#pragma unroll
        for (int v = 0; v < 2; ++v) {
            const int id = v * 256 + tid;
            const int row = id >> 3, c4 = id & 7;
            const float4 x = lds128f(src + row * 128 + c4 * 16);
            sts64(dst + row * 80 + c4 * 8, pack_h2(x.x, x.y), pack_h2(x.z, x.w));
        }
#pragma unroll
        for (int v = 0; v < 4; ++v) {
            const int id = v * 256 + tid;
            const int row = id >> 5, c4 = id & 31;
            const float4 x = lds128f(src + 8192 + row * 512 + c4 * 16);
            sts64(dst + 5120 + row * 272 + c4 * 8,
                  pack_h2(x.x, x.y), pack_h2(x.z, x.w));
        }
    };

    // ---- prologue: 3 chunks queued, chunk 0 repacked ----
    issue_chunk(0); cp_commit();
    issue_chunk(1); cp_commit();
    issue_chunk(2); cp_commit();
    cp_wait<2>();          // chunk 0 landed (own writes)
    __syncthreads();       // all threads' chunk-0 writes visible
    repack(0);

    for (int t = 0; t < NST; ++t) {
        cp_wait<1>();      // chunk t+1 landed (chunk t+2 may pend)
        __syncthreads();   // cross-thread visibility; repack(t)/compute(t-1) done
        if (t + 1 < NST) repack(t + 1);          // stg[(t+1)%3] -> f16[(t+1)&1]
        if (t + 3 < NST) issue_chunk(t + 3);     // overwrites stg[t%3] (readers done)
        cp_commit();       // possibly-empty group keeps counting uniform

        const uint32_t base = sb + F16_BASE + (t & 1) * F16_STG;
        const uint32_t aa = base + a_off;
        const uint32_t bb = base + b_off;

#pragma unroll
        for (int kh = 0; kh < 2; ++kh) {
            uint32_t A0[4], A1[4], B0[4], B1[4];
            ldmx4(A0, aa + kh * 32);
            ldmx4(A1, aa + 1280 + kh * 32);        // +16 rows * 80B
            ldmx4t(B0, bb + kh * 4352);            // +16 k-rows * 272B
            ldmx4t(B1, bb + 32 + kh * 4352);       // +16 n (16 halves)

            mma_f16(acc[0][0], A0, &B0[0]);
            mma_f16(acc[0][1], A0, &B0[2]);
            mma_f16(acc[0][2], A0, &B1[0]);
            mma_f16(acc[0][3], A0, &B1[2]);
            mma_f16(acc[1][0], A1, &B0[0]);
            mma_f16(acc[1][1], A1, &B0[2]);
            mma_f16(acc[1][2], A1, &B1[0]);
            mma_f16(acc[1][3], A1, &B1[2]);
        }
    }

    // ---- epilogue: bias + relu (verified) ----
#pragma unroll
    for (int nt = 0; nt < 4; ++nt) {
        const int n0 = wn * 32 + nt * 8 + t4 * 2;
        const float2 bv = *reinterpret_cast<const float2*>(bias + n0);
#pragma unroll
        for (int mt = 0; mt < 2; ++mt) {
            const int m = wm * 32 + mt * 16 + g;
            float2 o0, o1;
            o0.x = fmaxf(acc[mt][nt][0] + bv.x, 0.f);
            o0.y = fmaxf(acc[mt][nt][1] + bv.y, 0.f);
            o1.x = fmaxf(acc[mt][nt][2] + bv.x, 0.f);
            o1.y = fmaxf(acc[mt][nt][3] + bv.y, 0.f);
            *reinterpret_cast<float2*>(out + ((size_t)m * 256 + l) * 128 + n0) = o0;
            *reinterpret_cast<float2*>(out + ((size_t)(m + 8) * 256 + l) * 128 + n0) = o1;
        }
    }
}

}  // namespace

extern "C" void kernel_launch(void* const* d_in, const int* in_sizes, int n_in,
                              void* d_out, int out_size) {
    const float* X    = (const float*)d_in[0];
    const float* filt = (const float*)d_in[1];
    const float* bias = (const float*)d_in[2];
    float* out        = (float*)d_out;

    cudaFuncSetAttribute(bioconv_cpa_kernel,
                         cudaFuncAttributeMaxDynamicSharedMemorySize, SMEM_BYTES);
    bioconv_cpa_kernel<<<256, 256, SMEM_BYTES>>>(X, filt, bias, out);
}